// round 5
// baseline (speedup 1.0000x reference)
#include <cuda_runtime.h>

typedef unsigned long long ull;

#define THREADS 256
#define SPC     32            // samples per CTA
#define NBLK    256           // 8192 / 32
#define DT      0.1f
#define HDT     0.05f
#define LOG2PI  1.83787706640934548356f

// Precomputed divergence matrix H[j][k] = W2[j][k] * sum_i W1[i][j]*W3[k][i]
__device__ float g_H[256 * 256];

// ---------------- packed f32x2 helpers ----------------
__device__ __forceinline__ ull pack2(float lo, float hi) {
    ull v;
    asm("mov.b64 %0, {%1,%2};" : "=l"(v)
        : "r"(__float_as_uint(lo)), "r"(__float_as_uint(hi)));
    return v;
}
__device__ __forceinline__ void unpack2(ull v, float& lo, float& hi) {
    unsigned a, b;
    asm("mov.b64 {%0,%1}, %2;" : "=r"(a), "=r"(b) : "l"(v));
    lo = __uint_as_float(a); hi = __uint_as_float(b);
}
__device__ __forceinline__ ull fma2(ull a, ull b, ull c) {
    ull d;
    asm("fma.rn.f32x2 %0, %1, %2, %3;" : "=l"(d) : "l"(a), "l"(b), "l"(c));
    return d;
}

// ---------------- shared-memory layout (float offsets) ----------------
#define OFF_W1T 0        // [j][0..15]=W1 z-rows, [16]=W1 t-row, [17]=b1; stride 20 -> 5120
#define OFF_B2  5120     // 256
#define OFF_W3  5376     // W3[k*16+i] -> 4096
#define OFF_B3  9472     // 16
#define OFF_Z   9488     // z_eval [s*17+i] -> 544
#define OFF_H1  10032    // h1T [j*32+s] (8192); ALIASED as h2 [s*256+k] in phase C
#define OFF_D1  18224    // d1T [j*32+s] (8192)
#define OFF_WD  26416    // per-warp div partials [w*32+s] (256)
#define OFF_DV  26672    // div[s] (32)
#define SMEM_FLOATS 26704
#define SMEM_BYTES (SMEM_FLOATS * 4)

// ---------------- precompute H ----------------
__global__ void comp_H(const float* __restrict__ W1,
                       const float* __restrict__ W2,
                       const float* __restrict__ W3) {
    int j = blockIdx.x;      // 0..255
    int k = threadIdx.x;     // 0..255
    float g = 0.0f;
#pragma unroll
    for (int i = 0; i < 16; i++)
        g = fmaf(W1[i * 256 + j], W3[k * 16 + i], g);
    g_H[j * 256 + k] = g * W2[j * 256 + k];
}

// ---------------- main CNF kernel ----------------
__global__ __launch_bounds__(THREADS, 2)
void cnf_kernel(const float* __restrict__ x,
                const float* __restrict__ W1, const float* __restrict__ b1,
                const float* __restrict__ W2, const float* __restrict__ b2,
                const float* __restrict__ W3, const float* __restrict__ b3,
                float* __restrict__ out) {
    extern __shared__ float sm[];
    const int tid  = threadIdx.x;
    const int lane = tid & 31;
    const int warp = tid >> 5;

    // ---- stage weights into shared ----
#pragma unroll
    for (int i = 0; i < 17; i++)
        sm[OFF_W1T + tid * 20 + i] = W1[i * 256 + tid];
    sm[OFF_W1T + tid * 20 + 17] = b1[tid];
    sm[OFF_B2 + tid] = b2[tid];
    for (int q = tid; q < 4096; q += THREADS) sm[OFF_W3 + q] = W3[q];
    if (tid < 16) sm[OFF_B3 + tid] = b3[tid];

    // ---- RK4 state mapping (phases A/C2): thread t -> sample s=t>>3, comps (i0,i0+1) ----
    const int s  = tid >> 3;
    const int i0 = (tid & 7) << 1;
    const int gid = blockIdx.x * SPC + s;
    float z0a = x[gid * 16 + i0];
    float z0b = x[gid * 16 + i0 + 1];
    sm[OFF_Z + s * 17 + i0]     = z0a;
    sm[OFF_Z + s * 17 + i0 + 1] = z0b;
    float ka = 0.0f, kb = 0.0f;
    float divsum = 0.0f;

    // ---- phase-B micro-tile mapping: warp -> 32-k block; lane = sq*8 + kq ----
    const int kq = lane & 7;          // k group of 4
    const int sq = lane >> 3;         // sample group of 8
    const int k0 = (warp << 5) + (kq << 2);
    const int s0 = sq << 3;
    const float* w2p = W2  + k0;
    const float* hpg = g_H + k0;
    __syncthreads();

    for (int st = 0; st < 10; ++st) {
        const float tn = (float)st * DT;
#pragma unroll 1
        for (int sub = 0; sub < 4; ++sub) {
            const float te = tn + ((sub == 0) ? 0.0f : ((sub == 3) ? DT : HDT));

            // ======== Phase A: layer 1. warp -> j range, lane -> sample ========
            {
                float zr[16];
#pragma unroll
                for (int i = 0; i < 16; i++) zr[i] = sm[OFF_Z + lane * 17 + i];
                const int jbase = warp << 5;
#pragma unroll 4
                for (int jj = 0; jj < 32; jj++) {
                    const int j = jbase + jj;
                    const float* wr = sm + OFF_W1T + j * 20;
                    float4 w0 = *(const float4*)(wr);
                    float4 w1v = *(const float4*)(wr + 4);
                    float4 w2v = *(const float4*)(wr + 8);
                    float4 w3v = *(const float4*)(wr + 12);
                    float2 tb = *(const float2*)(wr + 16);
                    float a = fmaf(te, tb.x, tb.y);
                    a = fmaf(zr[0],  w0.x, a);  a = fmaf(zr[1],  w0.y, a);
                    a = fmaf(zr[2],  w0.z, a);  a = fmaf(zr[3],  w0.w, a);
                    a = fmaf(zr[4],  w1v.x, a); a = fmaf(zr[5],  w1v.y, a);
                    a = fmaf(zr[6],  w1v.z, a); a = fmaf(zr[7],  w1v.w, a);
                    a = fmaf(zr[8],  w2v.x, a); a = fmaf(zr[9],  w2v.y, a);
                    a = fmaf(zr[10], w2v.z, a); a = fmaf(zr[11], w2v.w, a);
                    a = fmaf(zr[12], w3v.x, a); a = fmaf(zr[13], w3v.y, a);
                    a = fmaf(zr[14], w3v.z, a); a = fmaf(zr[15], w3v.w, a);
                    float e  = __expf(-a);
                    float sg = __fdividef(1.0f, 1.0f + e);
                    float h  = a * sg;                      // silu
                    float d  = fmaf(h, 1.0f - sg, sg);      // silu'
                    sm[OFF_H1 + j * 32 + lane] = h;
                    sm[OFF_D1 + j * 32 + lane] = d;
                }
            }
            __syncthreads();

            // ======== Phase B: register-tiled GEMMs (a2 and u) ========
            // thread tile: 4 sample-pairs (8 samples) x 4 k, for both GEMMs
            ull aA[16], aU[16];      // [sp*4+kk]; pair = (sample 2sp, 2sp+1)
            {
                const float4 b2v = *(const float4*)(sm + OFF_B2 + k0);
                const ull bs0 = pack2(b2v.x, b2v.x);
                const ull bs1 = pack2(b2v.y, b2v.y);
                const ull bs2 = pack2(b2v.z, b2v.z);
                const ull bs3 = pack2(b2v.w, b2v.w);
#pragma unroll
                for (int sp = 0; sp < 4; sp++) {
                    aA[sp * 4 + 0] = bs0; aA[sp * 4 + 1] = bs1;
                    aA[sp * 4 + 2] = bs2; aA[sp * 4 + 3] = bs3;
                    aU[sp * 4 + 0] = 0ULL; aU[sp * 4 + 1] = 0ULL;
                    aU[sp * 4 + 2] = 0ULL; aU[sp * 4 + 3] = 0ULL;
                }
#pragma unroll 4
                for (int j = 0; j < 256; j++) {
                    const float4 wv = __ldg((const float4*)(w2p + (j << 8)));
                    const float4 gv = __ldg((const float4*)(hpg + (j << 8)));
                    const ulonglong2 h01 = *(const ulonglong2*)(sm + OFF_H1 + (j << 5) + s0);
                    const ulonglong2 h23 = *(const ulonglong2*)(sm + OFF_H1 + (j << 5) + s0 + 4);
                    const ulonglong2 d01 = *(const ulonglong2*)(sm + OFF_D1 + (j << 5) + s0);
                    const ulonglong2 d23 = *(const ulonglong2*)(sm + OFF_D1 + (j << 5) + s0 + 4);
                    const ull hp[4] = {h01.x, h01.y, h23.x, h23.y};
                    const ull dp_[4] = {d01.x, d01.y, d23.x, d23.y};
                    const ull ws0 = pack2(wv.x, wv.x), ws1 = pack2(wv.y, wv.y);
                    const ull ws2 = pack2(wv.z, wv.z), ws3 = pack2(wv.w, wv.w);
                    const ull gs0 = pack2(gv.x, gv.x), gs1 = pack2(gv.y, gv.y);
                    const ull gs2 = pack2(gv.z, gv.z), gs3 = pack2(gv.w, gv.w);
#pragma unroll
                    for (int sp = 0; sp < 4; sp++) {
                        aA[sp * 4 + 0] = fma2(hp[sp], ws0, aA[sp * 4 + 0]);
                        aA[sp * 4 + 1] = fma2(hp[sp], ws1, aA[sp * 4 + 1]);
                        aA[sp * 4 + 2] = fma2(hp[sp], ws2, aA[sp * 4 + 2]);
                        aA[sp * 4 + 3] = fma2(hp[sp], ws3, aA[sp * 4 + 3]);
                        aU[sp * 4 + 0] = fma2(dp_[sp], gs0, aU[sp * 4 + 0]);
                        aU[sp * 4 + 1] = fma2(dp_[sp], gs1, aU[sp * 4 + 1]);
                        aU[sp * 4 + 2] = fma2(dp_[sp], gs2, aU[sp * 4 + 2]);
                        aU[sp * 4 + 3] = fma2(dp_[sp], gs3, aU[sp * 4 + 3]);
                    }
                }
            }

            // ======== Phase C1: silu on a2, divergence dot + kq reduce ========
            {
                ull dpv[4];
#pragma unroll
                for (int sp = 0; sp < 4; sp++) {
                    dpv[sp] = 0ULL;
#pragma unroll
                    for (int kk = 0; kk < 4; kk++) {
                        float a0, a1;
                        unpack2(aA[sp * 4 + kk], a0, a1);
                        float e0 = __expf(-a0), e1 = __expf(-a1);
                        float g0 = __fdividef(1.0f, 1.0f + e0);
                        float g1 = __fdividef(1.0f, 1.0f + e1);
                        float h0 = a0 * g0, h1 = a1 * g1;
                        float d0 = fmaf(h0, 1.0f - g0, g0);
                        float d1 = fmaf(h1, 1.0f - g1, g1);
                        aA[sp * 4 + kk] = pack2(h0, h1);           // keep h2
                        dpv[sp] = fma2(aU[sp * 4 + kk], pack2(d0, d1), dpv[sp]);
                    }
                }
                // reduce each sample's partial over the 8 kq lanes (lane bits 0..2)
                float dl[8];
#pragma unroll
                for (int sp = 0; sp < 4; sp++) unpack2(dpv[sp], dl[2 * sp], dl[2 * sp + 1]);
#pragma unroll
                for (int m2 = 0; m2 < 8; m2++) {
                    dl[m2] += __shfl_xor_sync(0xffffffffu, dl[m2], 1);
                    dl[m2] += __shfl_xor_sync(0xffffffffu, dl[m2], 2);
                    dl[m2] += __shfl_xor_sync(0xffffffffu, dl[m2], 4);
                }
                if (kq == 0) {
#pragma unroll
                    for (int m2 = 0; m2 < 8; m2++)
                        sm[OFF_WD + warp * 32 + s0 + m2] = dl[m2];
                }
            }
            __syncthreads();   // phase-B readers of h1T/d1T done; WD visible

            // ======== h2 store ([s][256]) + cross-warp div reduce ========
            {
#pragma unroll
                for (int sp = 0; sp < 4; sp++) {
                    float l0, h0, l1, h1, l2, h2v, l3, h3;
                    unpack2(aA[sp * 4 + 0], l0, h0);
                    unpack2(aA[sp * 4 + 1], l1, h1);
                    unpack2(aA[sp * 4 + 2], l2, h2v);
                    unpack2(aA[sp * 4 + 3], l3, h3);
                    float4 va = make_float4(l0, l1, l2, l3);
                    float4 vb = make_float4(h0, h1, h2v, h3);
                    *(float4*)(sm + OFF_H1 + (s0 + 2 * sp) * 256 + k0)     = va;
                    *(float4*)(sm + OFF_H1 + (s0 + 2 * sp + 1) * 256 + k0) = vb;
                }
                if (tid < 32) {
                    float dv = 0.0f;
#pragma unroll
                    for (int w = 0; w < 8; w++) dv += sm[OFF_WD + w * 32 + tid];
                    sm[OFF_DV + tid] = dv;
                }
            }
            __syncthreads();

            // ======== Phase C2: layer 3 + RK4 update. thread -> (s, i0) ========
            {
                ull fz = pack2(sm[OFF_B3 + i0], sm[OFF_B3 + i0 + 1]);
                const float* h2r = sm + OFF_H1 + s * 256;
#pragma unroll 4
                for (int k = 0; k < 256; k += 4) {
                    float4 hq = *(const float4*)(h2r + k);
                    fz = fma2(pack2(hq.x, hq.x), *(const ull*)(sm + OFF_W3 + (k + 0) * 16 + i0), fz);
                    fz = fma2(pack2(hq.y, hq.y), *(const ull*)(sm + OFF_W3 + (k + 1) * 16 + i0), fz);
                    fz = fma2(pack2(hq.z, hq.z), *(const ull*)(sm + OFF_W3 + (k + 2) * 16 + i0), fz);
                    fz = fma2(pack2(hq.w, hq.w), *(const ull*)(sm + OFF_W3 + (k + 3) * 16 + i0), fz);
                }
                float f0, f1;
                unpack2(fz, f0, f1);
                const float wgt = (sub == 1 || sub == 2) ? 2.0f : 1.0f;
                ka = fmaf(wgt, f0, ka);
                kb = fmaf(wgt, f1, kb);
                if ((tid & 7) == 0) divsum = fmaf(wgt, sm[OFF_DV + s], divsum);
                if (sub < 3) {
                    const float c = (sub == 2) ? DT : HDT;
                    sm[OFF_Z + s * 17 + i0]     = fmaf(c, f0, z0a);
                    sm[OFF_Z + s * 17 + i0 + 1] = fmaf(c, f1, z0b);
                } else {
                    z0a = fmaf(DT / 6.0f, ka, z0a);
                    z0b = fmaf(DT / 6.0f, kb, z0b);
                    ka = 0.0f; kb = 0.0f;
                    sm[OFF_Z + s * 17 + i0]     = z0a;
                    sm[OFF_Z + s * 17 + i0 + 1] = z0b;
                }
            }
            __syncthreads();
        }
    }

    // ---- final: logpz - logp1 ----
    float ss = z0a * z0a + z0b * z0b;
    ss += __shfl_xor_sync(0xffffffffu, ss, 1);
    ss += __shfl_xor_sync(0xffffffffu, ss, 2);
    ss += __shfl_xor_sync(0xffffffffu, ss, 4);
    if ((tid & 7) == 0)
        out[gid] = -0.5f * (ss + 16.0f * LOG2PI) + (DT / 6.0f) * divsum;
}

extern "C" void kernel_launch(void* const* d_in, const int* in_sizes, int n_in,
                              void* d_out, int out_size) {
    const float* x  = (const float*)d_in[0];
    const float* W1 = (const float*)d_in[1];
    const float* b1 = (const float*)d_in[2];
    const float* W2 = (const float*)d_in[3];
    const float* b2 = (const float*)d_in[4];
    const float* W3 = (const float*)d_in[5];
    const float* b3 = (const float*)d_in[6];
    float* out = (float*)d_out;

    comp_H<<<256, 256>>>(W1, W2, W3);

    cudaFuncSetAttribute(cnf_kernel, cudaFuncAttributeMaxDynamicSharedMemorySize,
                         SMEM_BYTES);
    cnf_kernel<<<NBLK, THREADS, SMEM_BYTES>>>(x, W1, b1, W2, b2, W3, b3, out);
}

// round 6
// speedup vs baseline: 1.0014x; 1.0014x over previous
#include <cuda_runtime.h>

typedef unsigned long long ull;

#define THREADS 256
#define SPC     32            // samples per CTA
#define NBLK    256           // 8192 / 32
#define DT      0.1f
#define HDT     0.05f
#define LOG2PI  1.83787706640934548356f

// Precomputed divergence matrix H[j][k] = W2[j][k] * sum_i W1[i][j]*W3[k][i]
__device__ float g_H[256 * 256];

// ---------------- packed f32x2 helpers ----------------
__device__ __forceinline__ ull pack2(float lo, float hi) {
    ull v;
    asm("mov.b64 %0, {%1,%2};" : "=l"(v)
        : "r"(__float_as_uint(lo)), "r"(__float_as_uint(hi)));
    return v;
}
__device__ __forceinline__ void unpack2(ull v, float& lo, float& hi) {
    unsigned a, b;
    asm("mov.b64 {%0,%1}, %2;" : "=r"(a), "=r"(b) : "l"(v));
    lo = __uint_as_float(a); hi = __uint_as_float(b);
}
__device__ __forceinline__ ull fma2(ull a, ull b, ull c) {
    ull d;
    asm("fma.rn.f32x2 %0, %1, %2, %3;" : "=l"(d) : "l"(a), "l"(b), "l"(c));
    return d;
}

// ---------------- shared-memory layout (float offsets) ----------------
#define OFF_W1T 0        // [j][0..15]=W1 z-rows, [16]=W1 t-row, [17]=b1; stride 20 -> 5120
#define OFF_B2  5120     // 256
#define OFF_W3  5376     // W3[k*16+i] -> 4096
#define OFF_B3  9472     // 16
#define OFF_Z   9488     // z_eval [s*17+i] -> 544
#define OFF_H1  10032    // h1T [j*32+s] (8192); ALIASED as h2 [s*256+k] in phase C
#define OFF_D1  18224    // d1T [j*32+s] (8192)
#define OFF_WD  26416    // per-warp div partials [w*32+s] (256)
#define OFF_DV  26672    // div[s] (32)
#define SMEM_FLOATS 26704
#define SMEM_BYTES (SMEM_FLOATS * 4)

// ---------------- precompute H ----------------
__global__ void comp_H(const float* __restrict__ W1,
                       const float* __restrict__ W2,
                       const float* __restrict__ W3) {
    int j = blockIdx.x;      // 0..255
    int k = threadIdx.x;     // 0..255
    float g = 0.0f;
#pragma unroll
    for (int i = 0; i < 16; i++)
        g = fmaf(W1[i * 256 + j], W3[k * 16 + i], g);
    g_H[j * 256 + k] = g * W2[j * 256 + k];
}

// ---------------- main CNF kernel ----------------
__global__ __launch_bounds__(THREADS, 2)
void cnf_kernel(const float* __restrict__ x,
                const float* __restrict__ W1, const float* __restrict__ b1,
                const float* __restrict__ W2, const float* __restrict__ b2,
                const float* __restrict__ W3, const float* __restrict__ b3,
                float* __restrict__ out) {
    extern __shared__ float sm[];
    const int tid  = threadIdx.x;
    const int lane = tid & 31;
    const int warp = tid >> 5;

    // ---- stage weights into shared ----
#pragma unroll
    for (int i = 0; i < 17; i++)
        sm[OFF_W1T + tid * 20 + i] = W1[i * 256 + tid];
    sm[OFF_W1T + tid * 20 + 17] = b1[tid];
    sm[OFF_B2 + tid] = b2[tid];
    for (int q = tid; q < 4096; q += THREADS) sm[OFF_W3 + q] = W3[q];
    if (tid < 16) sm[OFF_B3 + tid] = b3[tid];

    // ---- RK4 state mapping (phases A/C2): thread t -> sample s=t>>3, comps (i0,i0+1) ----
    const int s  = tid >> 3;
    const int i0 = (tid & 7) << 1;
    const int gid = blockIdx.x * SPC + s;
    float z0a = x[gid * 16 + i0];
    float z0b = x[gid * 16 + i0 + 1];
    sm[OFF_Z + s * 17 + i0]     = z0a;
    sm[OFF_Z + s * 17 + i0 + 1] = z0b;
    float ka = 0.0f, kb = 0.0f;
    float divsum = 0.0f;

    // ---- phase-B micro-tile mapping: warp -> 32-k block; lane = sq*8 + kq ----
    const int kq = lane & 7;          // k group of 4
    const int sq = lane >> 3;         // sample group of 8
    const int k0 = (warp << 5) + (kq << 2);
    const int s0 = sq << 3;
    const float* w2p = W2  + k0;
    const float* hpg = g_H + k0;
    __syncthreads();

    for (int st = 0; st < 10; ++st) {
        const float tn = (float)st * DT;
#pragma unroll 1
        for (int sub = 0; sub < 4; ++sub) {
            const float te = tn + ((sub == 0) ? 0.0f : ((sub == 3) ? DT : HDT));

            // ======== Phase A: layer 1. warp -> j range, lane -> sample ========
            {
                float zr[16];
#pragma unroll
                for (int i = 0; i < 16; i++) zr[i] = sm[OFF_Z + lane * 17 + i];
                const int jbase = warp << 5;
#pragma unroll 4
                for (int jj = 0; jj < 32; jj++) {
                    const int j = jbase + jj;
                    const float* wr = sm + OFF_W1T + j * 20;
                    float4 w0 = *(const float4*)(wr);
                    float4 w1v = *(const float4*)(wr + 4);
                    float4 w2v = *(const float4*)(wr + 8);
                    float4 w3v = *(const float4*)(wr + 12);
                    float2 tb = *(const float2*)(wr + 16);
                    float a = fmaf(te, tb.x, tb.y);
                    a = fmaf(zr[0],  w0.x, a);  a = fmaf(zr[1],  w0.y, a);
                    a = fmaf(zr[2],  w0.z, a);  a = fmaf(zr[3],  w0.w, a);
                    a = fmaf(zr[4],  w1v.x, a); a = fmaf(zr[5],  w1v.y, a);
                    a = fmaf(zr[6],  w1v.z, a); a = fmaf(zr[7],  w1v.w, a);
                    a = fmaf(zr[8],  w2v.x, a); a = fmaf(zr[9],  w2v.y, a);
                    a = fmaf(zr[10], w2v.z, a); a = fmaf(zr[11], w2v.w, a);
                    a = fmaf(zr[12], w3v.x, a); a = fmaf(zr[13], w3v.y, a);
                    a = fmaf(zr[14], w3v.z, a); a = fmaf(zr[15], w3v.w, a);
                    float e  = __expf(-a);
                    float sg = __fdividef(1.0f, 1.0f + e);
                    float h  = a * sg;                      // silu
                    float d  = fmaf(h, 1.0f - sg, sg);      // silu'
                    sm[OFF_H1 + j * 32 + lane] = h;
                    sm[OFF_D1 + j * 32 + lane] = d;
                }
            }
            __syncthreads();

            // ======== Phase B: register-tiled GEMMs (a2 and u) ========
            // thread tile: 4 sample-pairs (8 samples) x 4 k, for both GEMMs
            ull aA[16], aU[16];      // [sp*4+kk]; pair = (sample 2sp, 2sp+1)
            {
                const float4 b2v = *(const float4*)(sm + OFF_B2 + k0);
                const ull bs0 = pack2(b2v.x, b2v.x);
                const ull bs1 = pack2(b2v.y, b2v.y);
                const ull bs2 = pack2(b2v.z, b2v.z);
                const ull bs3 = pack2(b2v.w, b2v.w);
#pragma unroll
                for (int sp = 0; sp < 4; sp++) {
                    aA[sp * 4 + 0] = bs0; aA[sp * 4 + 1] = bs1;
                    aA[sp * 4 + 2] = bs2; aA[sp * 4 + 3] = bs3;
                    aU[sp * 4 + 0] = 0ULL; aU[sp * 4 + 1] = 0ULL;
                    aU[sp * 4 + 2] = 0ULL; aU[sp * 4 + 3] = 0ULL;
                }
#pragma unroll 4
                for (int j = 0; j < 256; j++) {
                    const float4 wv = __ldg((const float4*)(w2p + (j << 8)));
                    const float4 gv = __ldg((const float4*)(hpg + (j << 8)));
                    const ulonglong2 h01 = *(const ulonglong2*)(sm + OFF_H1 + (j << 5) + s0);
                    const ulonglong2 h23 = *(const ulonglong2*)(sm + OFF_H1 + (j << 5) + s0 + 4);
                    const ulonglong2 d01 = *(const ulonglong2*)(sm + OFF_D1 + (j << 5) + s0);
                    const ulonglong2 d23 = *(const ulonglong2*)(sm + OFF_D1 + (j << 5) + s0 + 4);
                    const ull hp[4] = {h01.x, h01.y, h23.x, h23.y};
                    const ull dp_[4] = {d01.x, d01.y, d23.x, d23.y};
                    const ull ws0 = pack2(wv.x, wv.x), ws1 = pack2(wv.y, wv.y);
                    const ull ws2 = pack2(wv.z, wv.z), ws3 = pack2(wv.w, wv.w);
                    const ull gs0 = pack2(gv.x, gv.x), gs1 = pack2(gv.y, gv.y);
                    const ull gs2 = pack2(gv.z, gv.z), gs3 = pack2(gv.w, gv.w);
#pragma unroll
                    for (int sp = 0; sp < 4; sp++) {
                        aA[sp * 4 + 0] = fma2(hp[sp], ws0, aA[sp * 4 + 0]);
                        aA[sp * 4 + 1] = fma2(hp[sp], ws1, aA[sp * 4 + 1]);
                        aA[sp * 4 + 2] = fma2(hp[sp], ws2, aA[sp * 4 + 2]);
                        aA[sp * 4 + 3] = fma2(hp[sp], ws3, aA[sp * 4 + 3]);
                        aU[sp * 4 + 0] = fma2(dp_[sp], gs0, aU[sp * 4 + 0]);
                        aU[sp * 4 + 1] = fma2(dp_[sp], gs1, aU[sp * 4 + 1]);
                        aU[sp * 4 + 2] = fma2(dp_[sp], gs2, aU[sp * 4 + 2]);
                        aU[sp * 4 + 3] = fma2(dp_[sp], gs3, aU[sp * 4 + 3]);
                    }
                }
            }

            // ======== Phase C1: silu on a2, divergence dot + kq reduce ========
            {
                ull dpv[4];
#pragma unroll
                for (int sp = 0; sp < 4; sp++) {
                    dpv[sp] = 0ULL;
#pragma unroll
                    for (int kk = 0; kk < 4; kk++) {
                        float a0, a1;
                        unpack2(aA[sp * 4 + kk], a0, a1);
                        float e0 = __expf(-a0), e1 = __expf(-a1);
                        float g0 = __fdividef(1.0f, 1.0f + e0);
                        float g1 = __fdividef(1.0f, 1.0f + e1);
                        float h0 = a0 * g0, h1 = a1 * g1;
                        float d0 = fmaf(h0, 1.0f - g0, g0);
                        float d1 = fmaf(h1, 1.0f - g1, g1);
                        aA[sp * 4 + kk] = pack2(h0, h1);           // keep h2
                        dpv[sp] = fma2(aU[sp * 4 + kk], pack2(d0, d1), dpv[sp]);
                    }
                }
                // reduce each sample's partial over the 8 kq lanes (lane bits 0..2)
                float dl[8];
#pragma unroll
                for (int sp = 0; sp < 4; sp++) unpack2(dpv[sp], dl[2 * sp], dl[2 * sp + 1]);
#pragma unroll
                for (int m2 = 0; m2 < 8; m2++) {
                    dl[m2] += __shfl_xor_sync(0xffffffffu, dl[m2], 1);
                    dl[m2] += __shfl_xor_sync(0xffffffffu, dl[m2], 2);
                    dl[m2] += __shfl_xor_sync(0xffffffffu, dl[m2], 4);
                }
                if (kq == 0) {
#pragma unroll
                    for (int m2 = 0; m2 < 8; m2++)
                        sm[OFF_WD + warp * 32 + s0 + m2] = dl[m2];
                }
            }
            __syncthreads();   // phase-B readers of h1T/d1T done; WD visible

            // ======== h2 store ([s][256]) + cross-warp div reduce ========
            {
#pragma unroll
                for (int sp = 0; sp < 4; sp++) {
                    float l0, h0, l1, h1, l2, h2v, l3, h3;
                    unpack2(aA[sp * 4 + 0], l0, h0);
                    unpack2(aA[sp * 4 + 1], l1, h1);
                    unpack2(aA[sp * 4 + 2], l2, h2v);
                    unpack2(aA[sp * 4 + 3], l3, h3);
                    float4 va = make_float4(l0, l1, l2, l3);
                    float4 vb = make_float4(h0, h1, h2v, h3);
                    *(float4*)(sm + OFF_H1 + (s0 + 2 * sp) * 256 + k0)     = va;
                    *(float4*)(sm + OFF_H1 + (s0 + 2 * sp + 1) * 256 + k0) = vb;
                }
                if (tid < 32) {
                    float dv = 0.0f;
#pragma unroll
                    for (int w = 0; w < 8; w++) dv += sm[OFF_WD + w * 32 + tid];
                    sm[OFF_DV + tid] = dv;
                }
            }
            __syncthreads();

            // ======== Phase C2: layer 3 + RK4 update. thread -> (s, i0) ========
            {
                ull fz = pack2(sm[OFF_B3 + i0], sm[OFF_B3 + i0 + 1]);
                const float* h2r = sm + OFF_H1 + s * 256;
#pragma unroll 4
                for (int k = 0; k < 256; k += 4) {
                    float4 hq = *(const float4*)(h2r + k);
                    fz = fma2(pack2(hq.x, hq.x), *(const ull*)(sm + OFF_W3 + (k + 0) * 16 + i0), fz);
                    fz = fma2(pack2(hq.y, hq.y), *(const ull*)(sm + OFF_W3 + (k + 1) * 16 + i0), fz);
                    fz = fma2(pack2(hq.z, hq.z), *(const ull*)(sm + OFF_W3 + (k + 2) * 16 + i0), fz);
                    fz = fma2(pack2(hq.w, hq.w), *(const ull*)(sm + OFF_W3 + (k + 3) * 16 + i0), fz);
                }
                float f0, f1;
                unpack2(fz, f0, f1);
                const float wgt = (sub == 1 || sub == 2) ? 2.0f : 1.0f;
                ka = fmaf(wgt, f0, ka);
                kb = fmaf(wgt, f1, kb);
                if ((tid & 7) == 0) divsum = fmaf(wgt, sm[OFF_DV + s], divsum);
                if (sub < 3) {
                    const float c = (sub == 2) ? DT : HDT;
                    sm[OFF_Z + s * 17 + i0]     = fmaf(c, f0, z0a);
                    sm[OFF_Z + s * 17 + i0 + 1] = fmaf(c, f1, z0b);
                } else {
                    z0a = fmaf(DT / 6.0f, ka, z0a);
                    z0b = fmaf(DT / 6.0f, kb, z0b);
                    ka = 0.0f; kb = 0.0f;
                    sm[OFF_Z + s * 17 + i0]     = z0a;
                    sm[OFF_Z + s * 17 + i0 + 1] = z0b;
                }
            }
            __syncthreads();
        }
    }

    // ---- final: logpz - logp1 ----
    float ss = z0a * z0a + z0b * z0b;
    ss += __shfl_xor_sync(0xffffffffu, ss, 1);
    ss += __shfl_xor_sync(0xffffffffu, ss, 2);
    ss += __shfl_xor_sync(0xffffffffu, ss, 4);
    if ((tid & 7) == 0)
        out[gid] = -0.5f * (ss + 16.0f * LOG2PI) + (DT / 6.0f) * divsum;
}

extern "C" void kernel_launch(void* const* d_in, const int* in_sizes, int n_in,
                              void* d_out, int out_size) {
    const float* x  = (const float*)d_in[0];
    const float* W1 = (const float*)d_in[1];
    const float* b1 = (const float*)d_in[2];
    const float* W2 = (const float*)d_in[3];
    const float* b2 = (const float*)d_in[4];
    const float* W3 = (const float*)d_in[5];
    const float* b3 = (const float*)d_in[6];
    float* out = (float*)d_out;

    comp_H<<<256, 256>>>(W1, W2, W3);

    cudaFuncSetAttribute(cnf_kernel, cudaFuncAttributeMaxDynamicSharedMemorySize,
                         SMEM_BYTES);
    cnf_kernel<<<NBLK, THREADS, SMEM_BYTES>>>(x, W1, b1, W2, b2, W3, b3, out);
}